// round 12
// baseline (speedup 1.0000x reference)
#include <cuda_runtime.h>
#include <cstdint>

#define NN    200000
#define DIM   20
#define EE    6400000
#define ITERS 3
#define NBLK  ((NN + 255) / 256)   // 782 scan blocks
#define LIFE_DROP 255

typedef unsigned long long ull;

// Persistent scratch (allocations banned; __device__ globals are the workaround)
__device__ __align__(16) float g_h[(size_t)NN * DIM];
__device__ __align__(16) float g_x[(size_t)NN * DIM];
__device__ unsigned char g_depth8[NN];
// Weight image: [m*200 + k*10 + jp] = (W_m[2jp][k], W_m[2jp+1][k]),
// m in {Wz,Uz,Wr,Ur,Wh,Uh}; biases combined W+U at [1200 + g*10 + jp], g=z,r,h.
__device__ __align__(16) float2 g_stage[1232];
// CSR-by-dst with life classes: A = alive all 3 iters, B = iters 0-1, C = iter 0
__device__ int g_degA[NN];
__device__ int g_degB[NN];
__device__ int g_degC[NN];
__device__ int g_curA[NN];   // after fill: end of A region per node
__device__ int g_curB[NN];   // after fill: end of B region per node
__device__ int g_curC[NN];
__device__ int g_off[NN + 1];
__device__ int g_bsum[1024];
__device__ int g_boff[1024];
__device__ __align__(4) unsigned char g_elife[EE];
__device__ int g_csr[EE];

// ---------------------------------------------------------------------------
// packed f32x2 helpers
// ---------------------------------------------------------------------------
#define FMA2(d, a, b, c) \
    asm("fma.rn.f32x2 %0, %1, %2, %3;" : "=l"(d) : "l"(a), "l"(b), "l"(c))
#define PACK2(d, lo, hi) \
    asm("mov.b64 %0, {%1, %2};" : "=l"(d) : "f"(lo), "f"(hi))
#define UNPACK2(lo, hi, s) \
    asm("mov.b64 {%0, %1}, %2;" : "=f"(lo), "=f"(hi) : "l"(s))

__device__ __forceinline__ float fsigmoid(float v) {
    return 1.f / (1.f + __expf(-v));
}
__device__ __forceinline__ float ftanh(float x) {
    return fmaf(2.f, 1.f / (1.f + __expf(-2.f * x)), -1.f);
}

// ---------------------------------------------------------------------------
// prep (fused init): copy h, pack depth, zero counters, pack weights/biases
// ---------------------------------------------------------------------------
struct WParams {
    const float* W[6];   // Wz, Uz, Wr, Ur, Wh, Uh   ([DIM,DIM], row = out)
    const float* B[6];   // bz, buz, br, bur, bh, buh
};

__global__ void prep_kernel(const float* __restrict__ h_in,
                            const int* __restrict__ depth, WParams p) {
    int i = blockIdx.x * blockDim.x + threadIdx.x;
    const int n4 = NN * DIM / 4;
    if (i < n4)
        reinterpret_cast<float4*>(g_h)[i] = reinterpret_cast<const float4*>(h_in)[i];
    if (i < NN) {
        g_depth8[i] = (unsigned char)__ldg(depth + i);
        g_degA[i] = 0; g_degB[i] = 0; g_degC[i] = 0;
    }
    if (i < 1200) {
        int m = i / 200, r = i % 200;
        int k = r / 10, jp = r % 10;
        const float* w = p.W[m];
        g_stage[m * 200 + k * 10 + jp] =
            make_float2(w[(2 * jp) * DIM + k], w[(2 * jp + 1) * DIM + k]);
    } else if (i < 1230) {
        int t = i - 1200;
        int g = t / 10, jp = t % 10;
        const float* b0 = p.B[2 * g];
        const float* b1 = p.B[2 * g + 1];
        g_stage[1200 + g * 10 + jp] =
            make_float2(b0[2 * jp] + b1[2 * jp], b0[2 * jp + 1] + b1[2 * jp + 1]);
    } else if (i < 1232) {
        g_stage[i] = make_float2(0.f, 0.f);
    }
}

// ---------------------------------------------------------------------------
// CSR build: class histogram -> scan -> class-ordered fill (as R9)
// ---------------------------------------------------------------------------
__global__ void hist_kernel(const int4* __restrict__ esrc4,
                            const int4* __restrict__ edst4) {
    int t = blockIdx.x * blockDim.x + threadIdx.x;
    if (t >= EE / 4) return;
    int4 s4 = __ldg(esrc4 + t);
    int4 d4 = __ldg(edst4 + t);
    int ss[4] = { s4.x, s4.y, s4.z, s4.w };
    int dd[4] = { d4.x, d4.y, d4.z, d4.w };
    unsigned char lf[4];
#pragma unroll
    for (int k = 0; k < 4; k++) {
        int maxd = max((int)g_depth8[ss[k]], (int)g_depth8[dd[k]]);
        unsigned char life = LIFE_DROP;
        if (maxd <= 3) {
            life = (unsigned char)(3 - maxd);
            if (life >= 2)      atomicAdd(&g_degA[dd[k]], 1);
            else if (life == 1) atomicAdd(&g_degB[dd[k]], 1);
            else                atomicAdd(&g_degC[dd[k]], 1);
        }
        lf[k] = life;
    }
    reinterpret_cast<uchar4*>(g_elife)[t] = make_uchar4(lf[0], lf[1], lf[2], lf[3]);
}

__global__ void scanA_kernel() {
    __shared__ int sm[256];
    int i = blockIdx.x * 256 + threadIdx.x;
    int v = (i < NN) ? (g_degA[i] + g_degB[i] + g_degC[i]) : 0;
    sm[threadIdx.x] = v;
    __syncthreads();
    for (int off = 128; off > 0; off >>= 1) {
        if (threadIdx.x < off) sm[threadIdx.x] += sm[threadIdx.x + off];
        __syncthreads();
    }
    if (threadIdx.x == 0) g_bsum[blockIdx.x] = sm[0];
}

__global__ void scanB_kernel() {
    __shared__ int sm[1024];
    int t = threadIdx.x;
    int v = (t < NBLK) ? g_bsum[t] : 0;
    sm[t] = v;
    __syncthreads();
    for (int off = 1; off < 1024; off <<= 1) {
        int add = (t >= off) ? sm[t - off] : 0;
        __syncthreads();
        sm[t] += add;
        __syncthreads();
    }
    if (t < NBLK) g_boff[t] = sm[t] - v;
}

__global__ void scanC_kernel() {
    __shared__ int sm[256];
    int i = blockIdx.x * 256 + threadIdx.x;
    int a = 0, b = 0, c = 0;
    if (i < NN) { a = g_degA[i]; b = g_degB[i]; c = g_degC[i]; }
    int v = a + b + c;
    sm[threadIdx.x] = v;
    __syncthreads();
    for (int off = 1; off < 256; off <<= 1) {
        int add = (threadIdx.x >= off) ? sm[threadIdx.x - off] : 0;
        __syncthreads();
        sm[threadIdx.x] += add;
        __syncthreads();
    }
    if (i < NN) {
        int pos = g_boff[blockIdx.x] + sm[threadIdx.x] - v;
        g_off[i]  = pos;
        g_curA[i] = pos;
        g_curB[i] = pos + a;
        g_curC[i] = pos + a + b;
        if (i == NN - 1) g_off[NN] = g_boff[blockIdx.x] + sm[threadIdx.x];
    }
}

__global__ void fill_kernel(const int4* __restrict__ esrc4,
                            const int4* __restrict__ edst4) {
    int t = blockIdx.x * blockDim.x + threadIdx.x;
    if (t >= EE / 4) return;
    uchar4 l4 = reinterpret_cast<const uchar4*>(g_elife)[t];
    unsigned char lf[4] = { l4.x, l4.y, l4.z, l4.w };
    int4 s4 = __ldg(esrc4 + t);
    int4 d4 = __ldg(edst4 + t);
    int ss[4] = { s4.x, s4.y, s4.z, s4.w };
    int dd[4] = { d4.x, d4.y, d4.z, d4.w };
#pragma unroll
    for (int k = 0; k < 4; k++) {
        unsigned char life = lf[k];
        if (life == LIFE_DROP) continue;
        int d = dd[k];
        int* cur = (life >= 2) ? &g_curA[d] : (life == 1) ? &g_curB[d] : &g_curC[d];
        int pos = atomicAdd(cur, 1);
        g_csr[pos] = ss[k];
    }
}
// After fill: g_curA[u] = end of A region, g_curB[u] = end of B region.

// ---------------------------------------------------------------------------
// gather: x[u] = sum of h[src] over class prefix for this iteration (as R9)
// ---------------------------------------------------------------------------
__global__ void gather_kernel(int iter, int thr) {
    int lane = threadIdx.x & 31;
    if (lane >= 30) return;                        // 6 groups of 5 per warp
    int warp = (blockIdx.x * blockDim.x + threadIdx.x) >> 5;
    int u = warp * 6 + lane / 5;
    if (u >= NN) return;
    if (g_depth8[u] > thr) return;
    int c = lane % 5;

    int beg = g_off[u];
    int end = (iter == 0) ? g_off[u + 1]
            : (iter == 1) ? g_curB[u]
                          : g_curA[u];
    float4 acc = make_float4(0.f, 0.f, 0.f, 0.f);
    int e = beg;
    for (; e + 2 <= end; e += 2) {
        int s0 = g_csr[e];
        int s1 = g_csr[e + 1];
        float4 v0 = __ldg(reinterpret_cast<const float4*>(g_h + (size_t)s0 * DIM) + c);
        float4 v1 = __ldg(reinterpret_cast<const float4*>(g_h + (size_t)s1 * DIM) + c);
        acc.x += v0.x + v1.x; acc.y += v0.y + v1.y;
        acc.z += v0.z + v1.z; acc.w += v0.w + v1.w;
    }
    if (e < end) {
        int s0 = g_csr[e];
        float4 v0 = __ldg(reinterpret_cast<const float4*>(g_h + (size_t)s0 * DIM) + c);
        acc.x += v0.x; acc.y += v0.y; acc.z += v0.z; acc.w += v0.w;
    }
    reinterpret_cast<float4*>(g_x + (size_t)u * DIM)[c] = acc;
}

// ---------------------------------------------------------------------------
// GRU update: 5 threads per node. Thread t owns weight pairs 2t,2t+1
// (outputs 4t..4t+3) -> all weight reads are LDS.128; x/h rows read via
// __ldg (broadcast within the 5-lane group); q exchanged with 20 shfl.
// ---------------------------------------------------------------------------
#define MM2(acc, off, b) { \
    ulonglong2 w2 = *reinterpret_cast<const ulonglong2*>(&sW[(off)]); \
    FMA2(acc[0], w2.x, b, acc[0]); \
    FMA2(acc[1], w2.y, b, acc[1]); }

__global__ void __launch_bounds__(256) gru_kernel(int thr,
                                                  float* __restrict__ out_final) {
    // ull offsets: Wz=0, Uz=200, Wr=400, Ur=600, Wh=800, Uh=1000,
    //              Bz=1200, Br=1210, Bh=1220 (each + 2*t)
    __shared__ __align__(16) ull sW[1232];
    {
        const float4* src = reinterpret_cast<const float4*>(g_stage);
        float4* dst = reinterpret_cast<float4*>(sW);
        for (int k = threadIdx.x; k < 616; k += blockDim.x)
            dst[k] = src[k];
    }
    __syncthreads();

    int lane = threadIdx.x & 31;
    if (lane >= 30) return;                            // 6 groups of 5 per warp
    int warp = (blockIdx.x * blockDim.x + threadIdx.x) >> 5;
    int t = lane % 5;                                  // chunk owned
    int u = warp * 6 + lane / 5;
    if (u >= NN) return;

    if (g_depth8[u] > thr) {                           // inactive node
        if (out_final)
            reinterpret_cast<float4*>(out_final + (size_t)u * DIM)[t] =
                make_float4(0.f, 0.f, 0.f, 0.f);
        return;                                        // h unchanged
    }

    const unsigned gmask = 0x1Fu << (lane - t);
    const int base_lane  = lane - t;
    const int t2 = 2 * t;

    // accumulators: 2 output-pairs per thread, biases preloaded (LDS.128)
    ull accz[2], accr[2], acch[2];
    {
        ulonglong2 bz = *reinterpret_cast<const ulonglong2*>(&sW[1200 + t2]);
        ulonglong2 br = *reinterpret_cast<const ulonglong2*>(&sW[1210 + t2]);
        ulonglong2 bh = *reinterpret_cast<const ulonglong2*>(&sW[1220 + t2]);
        accz[0] = bz.x; accz[1] = bz.y;
        accr[0] = br.x; accr[1] = br.y;
        acch[0] = bh.x; acch[1] = bh.y;
    }

    // ---- Phase A: x contributions (Wz, Wr, Wh) ----
    {
        const float4* xp = reinterpret_cast<const float4*>(g_x + (size_t)u * DIM);
#pragma unroll
        for (int c4 = 0; c4 < 5; c4++) {
            float4 a = __ldg(xp + c4);                 // group-broadcast L1 hit
            float xs[4] = { a.x, a.y, a.z, a.w };
#pragma unroll
            for (int j = 0; j < 4; j++) {
                int k = 4 * c4 + j;
                ull b;
                PACK2(b, xs[j], xs[j]);
                int o = k * 10 + t2;
                MM2(accz, o,       b);
                MM2(accr, o + 400, b);
                MM2(acch, o + 800, b);
            }
        }
    }

    // ---- Phase B: h contributions to z, r (Uz, Ur); keep my chunk ----
    float4 myh4;
    {
        const float4* hp = reinterpret_cast<const float4*>(g_h + (size_t)u * DIM);
#pragma unroll
        for (int c4 = 0; c4 < 5; c4++) {
            float4 a = __ldg(hp + c4);
            if (c4 == t) myh4 = a;
            float hs[4] = { a.x, a.y, a.z, a.w };
#pragma unroll
            for (int j = 0; j < 4; j++) {
                int k = 4 * c4 + j;
                ull b;
                PACK2(b, hs[j], hs[j]);
                int o = k * 10 + t2;
                MM2(accz, o + 200, b);
                MM2(accr, o + 600, b);
            }
        }
    }

    // ---- Phase C: r = sigmoid, qa = r * h (my 4 outputs) ----
    float qa[4];
    {
        float r0, r1, r2, r3;
        UNPACK2(r0, r1, accr[0]);
        UNPACK2(r2, r3, accr[1]);
        qa[0] = fsigmoid(r0) * myh4.x;
        qa[1] = fsigmoid(r1) * myh4.y;
        qa[2] = fsigmoid(r2) * myh4.z;
        qa[3] = fsigmoid(r3) * myh4.w;
    }

    // ---- Phase D: q contributions to candidate (Uh); q via shfl ----
    // (these shuffles synchronize the group: all h reads precede the h write)
#pragma unroll
    for (int k = 0; k < DIM; k++) {
        float qk = __shfl_sync(gmask, qa[k & 3], base_lane + (k >> 2));
        ull b;
        PACK2(b, qk, qk);
        MM2(acch, k * 10 + t2 + 1000, b);
    }

    // ---- Phase E: gates, blend, store my float4 chunk ----
    float z0, z1, z2, z3, c0, c1, c2, c3;
    UNPACK2(z0, z1, accz[0]);
    UNPACK2(z2, z3, accz[1]);
    UNPACK2(c0, c1, acch[0]);
    UNPACK2(c2, c3, acch[1]);
    float hc0 = ftanh(c0), hc1 = ftanh(c1), hc2 = ftanh(c2), hc3 = ftanh(c3);
    float4 o4;
    o4.x = hc0 + fsigmoid(z0) * (myh4.x - hc0);
    o4.y = hc1 + fsigmoid(z1) * (myh4.y - hc1);
    o4.z = hc2 + fsigmoid(z2) * (myh4.z - hc2);
    o4.w = hc3 + fsigmoid(z3) * (myh4.w - hc3);

    float* dstp = out_final ? out_final : g_h;
    reinterpret_cast<float4*>(dstp + (size_t)u * DIM)[t] = o4;
}

// ---------------------------------------------------------------------------
// launch
// ---------------------------------------------------------------------------
extern "C" void kernel_launch(void* const* d_in, const int* in_sizes, int n_in,
                              void* d_out, int out_size) {
    const float* h_in = nullptr;
    const int*   depth = nullptr;
    const int*   esrc = nullptr;
    const int*   edst = nullptr;
    const float* Ws[6] = {};
    const float* Bs[6] = {};
    int wi = 0, bi = 0, ei = 0;
    for (int i = 0; i < n_in; i++) {
        int s = in_sizes[i];
        if (s == NN * DIM)      h_in  = (const float*)d_in[i];
        else if (s == NN)       depth = (const int*)d_in[i];
        else if (s == EE) {
            if (ei == 0) esrc = (const int*)d_in[i];
            else         edst = (const int*)d_in[i];
            ei++;
        }
        else if (s == DIM * DIM && wi < 6) Ws[wi++] = (const float*)d_in[i];
        else if (s == DIM      && bi < 6)  Bs[bi++] = (const float*)d_in[i];
    }

    WParams p;
    for (int m = 0; m < 6; m++) { p.W[m] = Ws[m]; p.B[m] = Bs[m]; }

    float* out = (float*)d_out;

    const int n4       = NN * DIM / 4;
    const int cb_prep  = (n4 + 255) / 256;
    const int cb_edge4 = (EE / 4 + 255) / 256;
    const int cb_grp   = (NN + 47) / 48;   // 48 nodes per 256-thread block

    const int4* esrc4 = reinterpret_cast<const int4*>(esrc);
    const int4* edst4 = reinterpret_cast<const int4*>(edst);

    prep_kernel<<<cb_prep, 256>>>(h_in, depth, p);
    hist_kernel<<<cb_edge4, 256>>>(esrc4, edst4);
    scanA_kernel<<<NBLK, 256>>>();
    scanB_kernel<<<1, 1024>>>();
    scanC_kernel<<<NBLK, 256>>>();
    fill_kernel<<<cb_edge4, 256>>>(esrc4, edst4);

    for (int i = 0; i < ITERS; i++) {
        int thr = ITERS - i;   // active: depth <= ITERS - i
        gather_kernel<<<cb_grp, 256>>>(i, thr);
        gru_kernel<<<cb_grp, 256>>>(thr, (i == ITERS - 1) ? out : nullptr);
    }
}

// round 13
// speedup vs baseline: 1.2510x; 1.2510x over previous
#include <cuda_runtime.h>
#include <cstdint>

#define NN    200000
#define DIM   20
#define EE    6400000
#define ITERS 3
#define NBLK  ((NN + 255) / 256)   // 782 scan blocks
#define LIFE_DROP 255

typedef unsigned long long ull;

// Persistent scratch (allocations banned; __device__ globals are the workaround)
__device__ __align__(16) float g_h[(size_t)NN * DIM];
__device__ __align__(16) float g_x[(size_t)NN * DIM];
__device__ unsigned char g_depth8[NN];
// Weight image: [m*200 + k*10 + jp] = (W_m[2jp][k], W_m[2jp+1][k]),
// m in {Wz,Uz,Wr,Ur,Wh,Uh}; biases combined W+U at [1200 + g*10 + jp], g=z,r,h.
__device__ __align__(16) float2 g_stage[1232];
// CSR-by-dst with life classes: A = alive all 3 iters, B = iters 0-1, C = iter 0
__device__ int g_degA[NN];
__device__ int g_degB[NN];
__device__ int g_degC[NN];
__device__ int g_curA[NN];   // after fill: end of A region per node
__device__ int g_curB[NN];   // after fill: end of B region per node
__device__ int g_curC[NN];
__device__ int g_off[NN + 1];
__device__ int g_bsum[1024];
__device__ int g_scan_done;
__device__ __align__(4) unsigned char g_elife[EE];
__device__ int g_csr[EE];

// ---------------------------------------------------------------------------
// packed f32x2 helpers
// ---------------------------------------------------------------------------
#define FMA2(d, a, b, c) \
    asm("fma.rn.f32x2 %0, %1, %2, %3;" : "=l"(d) : "l"(a), "l"(b), "l"(c))
#define PACK2(d, lo, hi) \
    asm("mov.b64 %0, {%1, %2};" : "=l"(d) : "f"(lo), "f"(hi))
#define UNPACK2(lo, hi, s) \
    asm("mov.b64 {%0, %1}, %2;" : "=f"(lo), "=f"(hi) : "l"(s))

__device__ __forceinline__ float fsigmoid(float v) {
    return 1.f / (1.f + __expf(-v));
}
__device__ __forceinline__ float ftanh(float x) {
    return fmaf(2.f, 1.f / (1.f + __expf(-2.f * x)), -1.f);
}

// ---------------------------------------------------------------------------
// prep (fused init): copy h, pack depth, zero counters, pack weights/biases
// ---------------------------------------------------------------------------
struct WParams {
    const float* W[6];   // Wz, Uz, Wr, Ur, Wh, Uh   ([DIM,DIM], row = out)
    const float* B[6];   // bz, buz, br, bur, bh, buh
};

__global__ void prep_kernel(const float* __restrict__ h_in,
                            const int* __restrict__ depth, WParams p) {
    int i = blockIdx.x * blockDim.x + threadIdx.x;
    const int n4 = NN * DIM / 4;
    if (i == 0) g_scan_done = 0;
    if (i < n4)
        reinterpret_cast<float4*>(g_h)[i] = reinterpret_cast<const float4*>(h_in)[i];
    if (i < NN) {
        g_depth8[i] = (unsigned char)__ldg(depth + i);
        g_degA[i] = 0; g_degB[i] = 0; g_degC[i] = 0;
    }
    if (i < 1200) {
        int m = i / 200, r = i % 200;
        int k = r / 10, jp = r % 10;
        const float* w = p.W[m];
        g_stage[m * 200 + k * 10 + jp] =
            make_float2(w[(2 * jp) * DIM + k], w[(2 * jp + 1) * DIM + k]);
    } else if (i < 1230) {
        int t = i - 1200;
        int g = t / 10, jp = t % 10;
        const float* b0 = p.B[2 * g];
        const float* b1 = p.B[2 * g + 1];
        g_stage[1200 + g * 10 + jp] =
            make_float2(b0[2 * jp] + b1[2 * jp], b0[2 * jp + 1] + b1[2 * jp + 1]);
    } else if (i < 1232) {
        g_stage[i] = make_float2(0.f, 0.f);
    }
}

// ---------------------------------------------------------------------------
// CSR build: class histogram -> fused scan -> class-ordered fill
// ---------------------------------------------------------------------------
__global__ void hist_kernel(const int4* __restrict__ esrc4,
                            const int4* __restrict__ edst4) {
    int t = blockIdx.x * blockDim.x + threadIdx.x;
    if (t >= EE / 4) return;
    int4 s4 = __ldg(esrc4 + t);
    int4 d4 = __ldg(edst4 + t);
    int ss[4] = { s4.x, s4.y, s4.z, s4.w };
    int dd[4] = { d4.x, d4.y, d4.z, d4.w };
    unsigned char lf[4];
#pragma unroll
    for (int k = 0; k < 4; k++) {
        int maxd = max((int)g_depth8[ss[k]], (int)g_depth8[dd[k]]);
        unsigned char life = LIFE_DROP;
        if (maxd <= 3) {
            life = (unsigned char)(3 - maxd);
            if (life >= 2)      atomicAdd(&g_degA[dd[k]], 1);
            else if (life == 1) atomicAdd(&g_degB[dd[k]], 1);
            else                atomicAdd(&g_degC[dd[k]], 1);
        }
        lf[k] = life;
    }
    reinterpret_cast<uchar4*>(g_elife)[t] = make_uchar4(lf[0], lf[1], lf[2], lf[3]);
}

// Single-kernel scan: one wave (782 blocks << 1184 resident-block capacity),
// software grid barrier via arrival counter. Produces g_off + class cursors.
__global__ void __launch_bounds__(256) scan_kernel() {
    __shared__ int sm[256];
    int b = blockIdx.x;
    int i = b * 256 + threadIdx.x;

    int a = 0, bb = 0, c = 0;
    if (i < NN) { a = g_degA[i]; bb = g_degB[i]; c = g_degC[i]; }
    int v = a + bb + c;

    // inclusive scan within block (Hillis-Steele)
    sm[threadIdx.x] = v;
    __syncthreads();
    for (int off = 1; off < 256; off <<= 1) {
        int add = (threadIdx.x >= off) ? sm[threadIdx.x - off] : 0;
        __syncthreads();
        sm[threadIdx.x] += add;
        __syncthreads();
    }
    int incl = sm[threadIdx.x];
    int btot = sm[255];

    // publish block total, then grid-wide join
    if (threadIdx.x == 0) {
        g_bsum[b] = btot;
        __threadfence();
        atomicAdd(&g_scan_done, 1);
        while (atomicAdd(&g_scan_done, 0) < (int)gridDim.x) { }
    }
    __syncthreads();

    // cooperative base = sum of g_bsum[0..b)
    int part = 0;
    for (int t = threadIdx.x; t < b; t += 256) part += g_bsum[t];
    sm[threadIdx.x] = part;
    __syncthreads();
    for (int off = 128; off > 0; off >>= 1) {
        if (threadIdx.x < off) sm[threadIdx.x] += sm[threadIdx.x + off];
        __syncthreads();
    }
    int base = sm[0];

    if (i < NN) {
        int pos = base + incl - v;
        g_off[i]  = pos;
        g_curA[i] = pos;
        g_curB[i] = pos + a;
        g_curC[i] = pos + a + bb;
        if (i == NN - 1) g_off[NN] = base + incl;
    }
}

__global__ void fill_kernel(const int4* __restrict__ esrc4,
                            const int4* __restrict__ edst4) {
    int t = blockIdx.x * blockDim.x + threadIdx.x;
    if (t >= EE / 4) return;
    uchar4 l4 = reinterpret_cast<const uchar4*>(g_elife)[t];
    unsigned char lf[4] = { l4.x, l4.y, l4.z, l4.w };
    int4 s4 = __ldg(esrc4 + t);
    int4 d4 = __ldg(edst4 + t);
    int ss[4] = { s4.x, s4.y, s4.z, s4.w };
    int dd[4] = { d4.x, d4.y, d4.z, d4.w };
#pragma unroll
    for (int k = 0; k < 4; k++) {
        unsigned char life = lf[k];
        if (life == LIFE_DROP) continue;
        int d = dd[k];
        int* cur = (life >= 2) ? &g_curA[d] : (life == 1) ? &g_curB[d] : &g_curC[d];
        int pos = atomicAdd(cur, 1);
        g_csr[pos] = ss[k];
    }
}
// After fill: g_curA[u] = end of A region, g_curB[u] = end of B region.

// ---------------------------------------------------------------------------
// gather: x[u] = sum of h[src] over class prefix for this iteration (R9)
// ---------------------------------------------------------------------------
__global__ void gather_kernel(int iter, int thr) {
    int lane = threadIdx.x & 31;
    if (lane >= 30) return;                        // 6 groups of 5 per warp
    int warp = (blockIdx.x * blockDim.x + threadIdx.x) >> 5;
    int u = warp * 6 + lane / 5;
    if (u >= NN) return;
    if (g_depth8[u] > thr) return;
    int c = lane % 5;

    int beg = g_off[u];
    int end = (iter == 0) ? g_off[u + 1]
            : (iter == 1) ? g_curB[u]
                          : g_curA[u];
    float4 acc = make_float4(0.f, 0.f, 0.f, 0.f);
    int e = beg;
    for (; e + 2 <= end; e += 2) {
        int s0 = g_csr[e];
        int s1 = g_csr[e + 1];
        float4 v0 = __ldg(reinterpret_cast<const float4*>(g_h + (size_t)s0 * DIM) + c);
        float4 v1 = __ldg(reinterpret_cast<const float4*>(g_h + (size_t)s1 * DIM) + c);
        acc.x += v0.x + v1.x; acc.y += v0.y + v1.y;
        acc.z += v0.z + v1.z; acc.w += v0.w + v1.w;
    }
    if (e < end) {
        int s0 = g_csr[e];
        float4 v0 = __ldg(reinterpret_cast<const float4*>(g_h + (size_t)s0 * DIM) + c);
        acc.x += v0.x; acc.y += v0.y; acc.z += v0.z; acc.w += v0.w;
    }
    reinterpret_cast<float4*>(g_x + (size_t)u * DIM)[c] = acc;
}

// ---------------------------------------------------------------------------
// GRU update: 2 threads per node, register-diet (exact R9/R7 version).
// Thread `half` owns pair indices jp in [5*half, 5*half+5)
// -> outputs [10*half, 10*half+10).
// ---------------------------------------------------------------------------
__global__ void __launch_bounds__(256) gru_kernel(int thr,
                                                  float* __restrict__ out_final) {
    // ull offsets: Wz=0, Uz=200, Wr=400, Ur=600, Wh=800, Uh=1000,
    //              Bz=1200, Br=1210, Bh=1220 (each + 5*half + jp)
    __shared__ __align__(16) ull sW[1232];
    {
        const float4* src = reinterpret_cast<const float4*>(g_stage);
        float4* dst = reinterpret_cast<float4*>(sW);
        for (int t = threadIdx.x; t < 616; t += blockDim.x)
            dst[t] = src[t];
    }
    __syncthreads();

    int gid  = blockIdx.x * blockDim.x + threadIdx.x;
    int u    = gid >> 1;
    int half = gid & 1;
    bool inb = (u < NN);
    bool act = inb && (g_depth8[u] <= thr);
    unsigned mask = __ballot_sync(0xFFFFFFFFu, act);

    if (!act) {
        if (inb && out_final) {
            float2* o = reinterpret_cast<float2*>(out_final + (size_t)u * DIM + 10 * half);
            float2 z2 = make_float2(0.f, 0.f);
#pragma unroll
            for (int k = 0; k < 5; k++) o[k] = z2;
        }
        return;
    }

    const int base5 = half * 5;
    const bool lowhalf = (half == 0);

    ull accz[5], accr[5], acch[5];
#pragma unroll
    for (int jp = 0; jp < 5; jp++) {
        accz[jp] = sW[1200 + base5 + jp];
        accr[jp] = sW[1210 + base5 + jp];
        acch[jp] = sW[1220 + base5 + jp];
    }

    // ---- Phase A: x contributions (Wz, Wr, Wh); x consumed in chunks ----
    {
        const float4* xp = reinterpret_cast<const float4*>(g_x + (size_t)u * DIM);
#pragma unroll
        for (int c4 = 0; c4 < 5; c4++) {
            float4 a = xp[c4];
            float vals[4] = { a.x, a.y, a.z, a.w };
#pragma unroll
            for (int t = 0; t < 4; t++) {
                int k = 4 * c4 + t;
                ull b;
                PACK2(b, vals[t], vals[t]);
                int o = k * 10 + base5;
#pragma unroll
                for (int jp = 0; jp < 5; jp++) {
                    FMA2(accz[jp], sW[o +       jp], b, accz[jp]);
                    FMA2(accr[jp], sW[o + 400 + jp], b, accr[jp]);
                    FMA2(acch[jp], sW[o + 800 + jp], b, acch[jp]);
                }
            }
        }
    }

    // ---- Phase B: h contributions to z, r (Uz, Ur); keep only my 10 h's ----
    float myh[10];
    {
        const float4* hp = reinterpret_cast<const float4*>(g_h + (size_t)u * DIM);
#pragma unroll
        for (int c4 = 0; c4 < 5; c4++) {
            float4 a = hp[c4];
            float vals[4] = { a.x, a.y, a.z, a.w };
#pragma unroll
            for (int t = 0; t < 4; t++) {
                int k = 4 * c4 + t;
                if ((k < 10) == lowhalf) myh[k % 10] = vals[t];
                ull b;
                PACK2(b, vals[t], vals[t]);
                int o = k * 10 + base5;
#pragma unroll
                for (int jp = 0; jp < 5; jp++) {
                    FMA2(accz[jp], sW[o + 200 + jp], b, accz[jp]);
                    FMA2(accr[jp], sW[o + 600 + jp], b, accr[jp]);
                }
            }
        }
    }

    // ---- Phase C: r = sigmoid, qa = r * h (my 10 outputs) ----
    float qa[10];
#pragma unroll
    for (int jp = 0; jp < 5; jp++) {
        float r0, r1;
        UNPACK2(r0, r1, accr[jp]);
        qa[2*jp]     = fsigmoid(r0) * myh[2*jp];
        qa[2*jp + 1] = fsigmoid(r1) * myh[2*jp + 1];
    }

    // exchange q with partner (lane ^ 1); q_lo = outputs 0..9, q_hi = 10..19
    float q_lo[10], q_hi[10];
#pragma unroll
    for (int t = 0; t < 10; t++) {
        float other = __shfl_xor_sync(mask, qa[t], 1);
        q_lo[t] = lowhalf ? qa[t] : other;
        q_hi[t] = lowhalf ? other : qa[t];
    }

    // ---- Phase D: q contributions to candidate (Uh) ----
#pragma unroll
    for (int k = 0; k < DIM; k++) {
        float qk = (k < 10) ? q_lo[k] : q_hi[k - 10];
        ull b;
        PACK2(b, qk, qk);
        int o = k * 10 + base5 + 1000;
#pragma unroll
        for (int jp = 0; jp < 5; jp++)
            FMA2(acch[jp], sW[o + jp], b, acch[jp]);
    }

    // ---- Phase E: gates, blend, store my 10 outputs ----
    float* dstp = out_final ? (out_final + (size_t)u * DIM) : (g_h + (size_t)u * DIM);
    float2* d2 = reinterpret_cast<float2*>(dstp + 10 * half);
#pragma unroll
    for (int jp = 0; jp < 5; jp++) {
        float z0, z1, c0, c1;
        UNPACK2(z0, z1, accz[jp]);
        UNPACK2(c0, c1, acch[jp]);
        float zz0 = fsigmoid(z0), zz1 = fsigmoid(z1);
        float hc0 = ftanh(c0),    hc1 = ftanh(c1);
        d2[jp] = make_float2(hc0 + zz0 * (myh[2*jp]     - hc0),
                             hc1 + zz1 * (myh[2*jp + 1] - hc1));
    }
}

// ---------------------------------------------------------------------------
// launch
// ---------------------------------------------------------------------------
extern "C" void kernel_launch(void* const* d_in, const int* in_sizes, int n_in,
                              void* d_out, int out_size) {
    const float* h_in = nullptr;
    const int*   depth = nullptr;
    const int*   esrc = nullptr;
    const int*   edst = nullptr;
    const float* Ws[6] = {};
    const float* Bs[6] = {};
    int wi = 0, bi = 0, ei = 0;
    for (int i = 0; i < n_in; i++) {
        int s = in_sizes[i];
        if (s == NN * DIM)      h_in  = (const float*)d_in[i];
        else if (s == NN)       depth = (const int*)d_in[i];
        else if (s == EE) {
            if (ei == 0) esrc = (const int*)d_in[i];
            else         edst = (const int*)d_in[i];
            ei++;
        }
        else if (s == DIM * DIM && wi < 6) Ws[wi++] = (const float*)d_in[i];
        else if (s == DIM      && bi < 6)  Bs[bi++] = (const float*)d_in[i];
    }

    WParams p;
    for (int m = 0; m < 6; m++) { p.W[m] = Ws[m]; p.B[m] = Bs[m]; }

    float* out = (float*)d_out;

    const int n4       = NN * DIM / 4;
    const int cb_prep  = (n4 + 255) / 256;
    const int cb_edge4 = (EE / 4 + 255) / 256;
    const int cb_node2 = (2 * NN + 255) / 256;   // 2 threads per node
    const int cb_gath  = (NN + 47) / 48;         // 48 nodes per 256-thread block

    const int4* esrc4 = reinterpret_cast<const int4*>(esrc);
    const int4* edst4 = reinterpret_cast<const int4*>(edst);

    prep_kernel<<<cb_prep, 256>>>(h_in, depth, p);
    hist_kernel<<<cb_edge4, 256>>>(esrc4, edst4);
    scan_kernel<<<NBLK, 256>>>();
    fill_kernel<<<cb_edge4, 256>>>(esrc4, edst4);

    for (int i = 0; i < ITERS; i++) {
        int thr = ITERS - i;   // active: depth <= ITERS - i
        gather_kernel<<<cb_gath, 256>>>(i, thr);
        gru_kernel<<<cb_node2, 256>>>(thr, (i == ITERS - 1) ? out : nullptr);
    }
}